// round 11
// baseline (speedup 1.0000x reference)
#include <cuda_runtime.h>
#include <cstdint>
#include <cstddef>

#define B_   1024
#define NT   128
#define NY   128
#define C_   512
#define EOS_ 1

// Compact gathered coefficients: G[b][t][{pC,pI}][j], t slot 127 = pad.
// 128 MiB scratch (device .bss).
__device__ float4 g_G4[(size_t)B_ * NT * 2 * (NY / 4)];
// Per-batch publish flags: 2 when both (pred,I) gathers of batch b landed.
// Scan resets after consuming, so every launch starts clean.
__device__ int g_ready[B_];

// Padded SMEM row stride (floats): multiple of 4 (16B cp.async), %32==4.
#define RSTRIDE 516

__device__ __forceinline__ int ld_acquire(const int* p) {
  int v;
  asm volatile("ld.acquire.gpu.global.b32 %0, [%1];" : "=r"(v) : "l"(p) : "memory");
  return v;
}

// ---------------------------------------------------------------------------
// Phase 1: gather/transpose (R10-proven). CTA = one (batch, array):
//   blockIdx.x = b*2 + arr   (arr 0 = pred -> pC, arr 1 = I -> pI)
// 16-row groups, double-buffered cp.async.cg, skipping 16B chunks no target
// touches. Epilogue: one thread owns (t, j-quad) -> 4 LDS + 1 STG.128.
// Adds: PDL trigger at CTA start, per-batch release flag at CTA end.
// ---------------------------------------------------------------------------
__global__ __launch_bounds__(256, 3) void gather_kernel(
    const float* __restrict__ pred, const float* __restrict__ R,
    const float* __restrict__ I, const int* __restrict__ target) {
  // Allow the dependent scan grid to start launching once every gather CTA
  // is resident (i.e. during our final wave).
  asm volatile("griddepcontrol.launch_dependents;" ::: "memory");

  extern __shared__ float stage[];  // [2][16 * RSTRIDE]
  __shared__ int tgt_s[NT];
  __shared__ float rS[NY];
  __shared__ unsigned mask_s[4];    // 128-bit mask over 16B chunks

  const int b   = blockIdx.x >> 1;
  const int arr = blockIdx.x & 1;
  const int tid = threadIdx.x;
  float* g_G = (float*)g_G4;

  if (tid < 4) mask_s[tid] = 0u;
  if (tid < NT) tgt_s[tid] = target[b * NT + tid];
  if (tid < NY) {
    const int base = (b * NY + tid) * 3;
    rS[tid] = arr ? ((tid == NY - 1) ? 1.0f : R[base + 1]) : R[base];
  }
  __syncthreads();
  if (tid < NT - 1) {  // only t=0..126 are gathered
    const int cbit = tgt_s[tid] >> 2;
    atomicOr(&mask_s[cbit >> 5], 1u << (cbit & 31));
  }
  __syncthreads();

  const int cc = tid & 127;  // 16B chunk index
  const unsigned on = (mask_s[cc >> 5] >> (cc & 31)) & 1u;
  const int rbase = tid >> 7;  // 0 or 1
  const float* __restrict__ src_arr = arr ? I : pred;

  auto issue = [&](int g) {
    const int r0 = g * 16;
    const float* src = src_arr + ((size_t)b * NY + r0) * C_ + cc * 4;
    float* buf = stage + (g & 1) * (16 * RSTRIDE) + cc * 4;
#pragma unroll
    for (int p = 0; p < 8; ++p) {
      const int r = rbase + 2 * p;
      unsigned sa = (unsigned)__cvta_generic_to_shared(buf + r * RSTRIDE);
      const float* gp = src + (size_t)r * C_;
      asm volatile(
          "{ .reg .pred p0; setp.ne.u32 p0, %0, 0;"
          " @p0 cp.async.cg.shared.global [%1], [%2], 16; }"
          :: "r"(on), "r"(sa), "l"(gp) : "memory");
    }
    asm volatile("cp.async.commit_group;" ::: "memory");
  };

  issue(0);
  issue(1);

  // Epilogue mapping: jq = quad within 16-row group (0..3), tq = t base.
  const int jq = tid & 3;
  const int tq = tid >> 2;  // 0..63; t = tq + 64*p
  const int tt0 = (tq < NT - 1) ? tgt_s[tq] : 0;
  const int tt1 = (tq + 64 < NT - 1) ? tgt_s[tq + 64] : 0;

  for (int g = 0; g < 8; ++g) {
    if (g == 7) asm volatile("cp.async.wait_group 0;" ::: "memory");
    else        asm volatile("cp.async.wait_group 1;" ::: "memory");
    __syncthreads();

    const int r0 = g * 16;
    const float s0 = rS[r0 + jq * 4 + 0];
    const float s1 = rS[r0 + jq * 4 + 1];
    const float s2 = rS[r0 + jq * 4 + 2];
    const float s3 = rS[r0 + jq * 4 + 3];
    const float* buf = stage + (g & 1) * (16 * RSTRIDE) + (jq * 4) * RSTRIDE;

    {  // t = tq (always < 127 since tq <= 63)
      const float* col = buf + tt0;
      float4 v;
      v.x = col[0 * RSTRIDE] * s0;
      v.y = col[1 * RSTRIDE] * s1;
      v.z = col[2 * RSTRIDE] * s2;
      v.w = col[3 * RSTRIDE] * s3;
      *(float4*)&g_G[(((size_t)b * NT + tq) * 2 + arr) * NY + r0 + jq * 4] = v;
    }
    if (tq + 64 < NT - 1) {  // t = tq + 64 (skip t = 127)
      const float* col = buf + tt1;
      float4 v;
      v.x = col[0 * RSTRIDE] * s0;
      v.y = col[1 * RSTRIDE] * s1;
      v.z = col[2 * RSTRIDE] * s2;
      v.w = col[3 * RSTRIDE] * s3;
      *(float4*)&g_G[(((size_t)b * NT + tq + 64) * 2 + arr) * NY + r0 + jq * 4] = v;
    }
    __syncthreads();
    if (g + 2 < 8) issue(g + 2);
  }

  __syncthreads();
  if (tid == 0) {
    __threadfence();                // release G writes
    atomicAdd(&g_ready[b], 1);      // publish this (b, arr)
  }
}

// ---------------------------------------------------------------------------
// Phase 2 (R10-proven core): warp per batch; lane l owns j = 4l..4l+3.
// Affine (A,D) warp scan of x[j] = a[j] + d[j]*x[j-1]. Coefficient rows
// stream through a per-warp cp.async SMEM ring, PF=14. Waits on the batch
// flag before touching G (supports overlapped PDL launch; no-op when gather
// already finished).
// ---------------------------------------------------------------------------
#define PF 14

__global__ __launch_bounds__(128) void scan_kernel(
    const float* __restrict__ R, const int* __restrict__ target,
    float* __restrict__ out) {
  extern __shared__ float ring[];  // [4 warps][16 slots][256 floats] = 64 KB
  const int l = threadIdx.x & 31;
  const int w = threadIdx.x >> 5;
  const int b = blockIdx.x * 4 + w;
  const unsigned FULL = 0xffffffffu;

  float* wring = ring + w * (16 * 256);
  const float* __restrict__ gG = (const float*)g_G4;
  const size_t gbase = (size_t)b * NT * 256;

  // ----- setup that doesn't depend on G (overlaps the producer) -----
  unsigned em[4];
#pragma unroll
  for (int m = 0; m < 4; ++m) {
    const int tg = target[b * NT + l + 32 * m];
    em[m] = __ballot_sync(FULL, tg == EOS_);
  }

  float r2[4];
#pragma unroll
  for (int k = 0; k < 4; ++k)
    r2[k] = R[((size_t)b * NY + 4 * l + k) * 3 + 2];
  const float r2p = __shfl_up_sync(FULL, r2[3], 1);
  const float dsh0 = (l == 0) ? 1.0f : r2p;

  const bool eos0 = em[0] & 1u;
  const float m0v = (l == 0) ? 1.0f : (eos0 ? 1.0f : r2[0]);
  const float m1v = eos0 ? 1.0f : r2[1];
  const float m2v = eos0 ? 1.0f : r2[2];
  const float m3v = eos0 ? 1.0f : r2[3];
  const float P0 = m0v, P1 = P0 * m1v, P2 = P1 * m2v, P3 = P2 * m3v;
  float Pw = P3;
#pragma unroll
  for (int off = 1; off < 32; off <<= 1) {
    const float Po = __shfl_up_sync(FULL, Pw, off);
    if (l >= off) Pw *= Po;
  }
  float pin = __shfl_up_sync(FULL, Pw, 1);
  if (l == 0) pin = 1.0f;
  float row0 = P0 * pin, row1 = P1 * pin, row2 = P2 * pin, row3 = P3 * pin;

  // ----- wait for this batch's two gather CTAs (R7-proven protocol) -----
  if (l == 0) {
    int ns = 64;
    while (ld_acquire(&g_ready[b]) < 2) {
      __nanosleep(ns);
      if (ns < 2048) ns <<= 1;
    }
  }
  __syncwarp(FULL);
  (void)ld_acquire(&g_ready[b]);  // per-lane acquire before cp.async reads

  auto issue_row = [&](int r) {
    const float* s1 = gG + gbase + (size_t)r * 256 + l * 4;
    float* d1 = wring + (r & 15) * 256 + l * 4;
    unsigned da = (unsigned)__cvta_generic_to_shared(d1);
    asm volatile(
        "cp.async.cg.shared.global [%0], [%1], 16;\n"
        "cp.async.cg.shared.global [%2], [%3], 16;\n"
        :: "r"(da), "l"(s1), "r"(da + 512), "l"(s1 + 128) : "memory");
    asm volatile("cp.async.commit_group;" ::: "memory");
  };

#pragma unroll
  for (int k = 0; k < PF; ++k) issue_row(k);

  asm volatile("cp.async.wait_group 13;" ::: "memory");  // row 0 ready
  float4 cpc = *(const float4*)(wring + 0 * 256 + l * 4);
  float4 cpi = *(const float4*)(wring + 0 * 256 + 128 + l * 4);

  for (int i = 0; i < NT - 1; ++i) {
    const int rf = i + PF;
    if (rf <= 127) issue_row(rf);
    else asm volatile("cp.async.commit_group;" ::: "memory");

    asm volatile("cp.async.wait_group 13;" ::: "memory");
    const int slot = (i + 1) & 15;
    const float4 npc = *(const float4*)(wring + slot * 256 + l * 4);
    const float4 npi = *(const float4*)(wring + slot * 256 + 128 + l * 4);

    const int ts = i + 1;
    const unsigned ew = (ts & 64) ? ((ts & 32) ? em[3] : em[2])
                                  : ((ts & 32) ? em[1] : em[0]);
    const bool eos = (ew >> (ts & 31)) & 1u;
    const float d0 = eos ? 1.0f : dsh0;
    const float d1 = eos ? 1.0f : r2[0];
    const float d2 = eos ? 1.0f : r2[1];
    const float d3 = eos ? 1.0f : r2[2];

    // a_full[j] = row[j-1]*pC[j-1] + row[j]*pI[j]   (j=0: row[0]*pI[0])
    const float q3 = row3 * cpc.w;
    float qp = __shfl_up_sync(FULL, q3, 1);
    if (l == 0) qp = 0.0f;
    const float a0 = fmaf(row0, cpi.x, qp);
    const float a1 = fmaf(row1, cpi.y, row0 * cpc.x);
    const float a2 = fmaf(row2, cpi.z, row1 * cpc.y);
    const float a3 = fmaf(row3, cpi.w, row2 * cpc.z);

    const float A0 = a0, D0 = d0;
    const float A1 = fmaf(d1, A0, a1), D1 = d1 * D0;
    const float A2 = fmaf(d2, A1, a2), D2 = d2 * D1;
    const float A3 = fmaf(d3, A2, a3), D3 = d3 * D2;

    float As = A3, Ds = D3;
#pragma unroll
    for (int off = 1; off < 32; off <<= 1) {
      const float Ao = __shfl_up_sync(FULL, As, off);
      const float Do = __shfl_up_sync(FULL, Ds, off);
      if (l >= off) { As = fmaf(Ds, Ao, As); Ds *= Do; }
    }
    float xin = __shfl_up_sync(FULL, As, 1);
    if (l == 0) xin = 0.0f;

    row0 = fmaf(D0, xin, A0);
    row1 = fmaf(D1, xin, A1);
    row2 = fmaf(D2, xin, A2);
    row3 = As;

    cpc = npc; cpi = npi;
  }

  if (l == 31) out[b] = row3;
  __syncwarp(FULL);
  if (l == 0) g_ready[b] = 0;  // reset for the next launch / replay
}

// ---------------------------------------------------------------------------
extern "C" void kernel_launch(void* const* d_in, const int* in_sizes, int n_in,
                              void* d_out, int out_size) {
  const float* pred   = (const float*)d_in[0];
  const float* R      = (const float*)d_in[1];
  const float* I      = (const float*)d_in[2];
  const int*   target = (const int*)d_in[3];

  const int smem_g = 2 * 16 * RSTRIDE * (int)sizeof(float);  // 66048 B
  cudaFuncSetAttribute(gather_kernel,
                       cudaFuncAttributeMaxDynamicSharedMemorySize, smem_g);
  const int smem_s = 4 * 16 * 256 * (int)sizeof(float);      // 65536 B
  cudaFuncSetAttribute(scan_kernel,
                       cudaFuncAttributeMaxDynamicSharedMemorySize, smem_s);

  gather_kernel<<<B_ * 2, 256, smem_g>>>(pred, R, I, target);

  // Scan via PDL so its CTAs launch during gather's final wave; the per-batch
  // flags provide the real data dependency. Fall back to a plain (stream-
  // ordered) launch if the attribute path is unavailable.
  cudaLaunchConfig_t cfg = {};
  cfg.gridDim = dim3(B_ / 4);
  cfg.blockDim = dim3(128);
  cfg.dynamicSmemBytes = smem_s;
  cfg.stream = 0;
  cudaLaunchAttribute attr[1];
  attr[0].id = cudaLaunchAttributeProgrammaticStreamSerialization;
  attr[0].val.programmaticStreamSerializationAllowed = 1;
  cfg.attrs = attr;
  cfg.numAttrs = 1;
  cudaError_t e = cudaLaunchKernelEx(&cfg, scan_kernel, R, target,
                                     (float*)d_out);
  if (e != cudaSuccess) {
    scan_kernel<<<B_ / 4, 128, smem_s>>>(R, target, (float*)d_out);
  }
}

// round 12
// speedup vs baseline: 3.2276x; 3.2276x over previous
#include <cuda_runtime.h>
#include <cstdint>
#include <cstddef>

#define B_   1024
#define NT   128
#define NY   128
#define C_   512
#define EOS_ 1

// Compact gathered coefficients: G[b][t][{pC,pI}][j], t slot 127 = pad.
// 128 MiB scratch (device .bss).
__device__ float4 g_G4[(size_t)B_ * NT * 2 * (NY / 4)];

// Padded SMEM row stride (floats): multiple of 4 (16B cp.async), %32==4.
#define RSTRIDE 516
#define GROWS   8                    // rows per pipeline group
#define NSTAGE  3                    // pipeline depth
#define NGROUP  (NY / GROWS)         // 16 groups per (b, arr)
#define SMEM_G  (NSTAGE * GROWS * RSTRIDE * 4)  // 49536 B -> 4 CTAs/SM

// ---------------------------------------------------------------------------
// Phase 1: gather/transpose. CTA = one (batch, array):
//   blockIdx.x = b*2 + arr   (arr 0 = pred -> pC, arr 1 = I -> pI)
// 8-row groups, 3-stage cp.async.cg pipeline, skipping 16B chunks no target
// touches. Epilogue: one thread owns (t, j-quad) -> 4 LDS + 1 STG.128.
// ---------------------------------------------------------------------------
__global__ __launch_bounds__(256, 4) void gather_kernel(
    const float* __restrict__ pred, const float* __restrict__ R,
    const float* __restrict__ I, const int* __restrict__ target) {
  extern __shared__ float stage[];  // [NSTAGE][GROWS * RSTRIDE]
  __shared__ int tgt_s[NT];
  __shared__ float rS[NY];
  __shared__ unsigned mask_s[4];    // 128-bit mask over 16B chunks

  const int b   = blockIdx.x >> 1;
  const int arr = blockIdx.x & 1;
  const int tid = threadIdx.x;
  float* g_G = (float*)g_G4;

  if (tid < 4) mask_s[tid] = 0u;
  if (tid < NT) tgt_s[tid] = target[b * NT + tid];
  if (tid < NY) {
    const int base = (b * NY + tid) * 3;
    rS[tid] = arr ? ((tid == NY - 1) ? 1.0f : R[base + 1]) : R[base];
  }
  __syncthreads();
  if (tid < NT - 1) {  // only t=0..126 are gathered
    const int cbit = tgt_s[tid] >> 2;
    atomicOr(&mask_s[cbit >> 5], 1u << (cbit & 31));
  }
  __syncthreads();

  const int cc = tid & 127;  // 16B chunk index
  const unsigned on = (mask_s[cc >> 5] >> (cc & 31)) & 1u;
  const int rbase = tid >> 7;  // 0 or 1
  const float* __restrict__ src_arr = arr ? I : pred;

  auto issue = [&](int g, int st) {
    const int r0 = g * GROWS;
    const float* src = src_arr + ((size_t)b * NY + r0) * C_ + cc * 4;
    float* buf = stage + st * (GROWS * RSTRIDE) + cc * 4;
#pragma unroll
    for (int p = 0; p < GROWS / 2; ++p) {
      const int r = rbase + 2 * p;
      unsigned sa = (unsigned)__cvta_generic_to_shared(buf + r * RSTRIDE);
      const float* gp = src + (size_t)r * C_;
      asm volatile(
          "{ .reg .pred p0; setp.ne.u32 p0, %0, 0;"
          " @p0 cp.async.cg.shared.global [%1], [%2], 16; }"
          :: "r"(on), "r"(sa), "l"(gp) : "memory");
    }
    asm volatile("cp.async.commit_group;" ::: "memory");
  };

  issue(0, 0); issue(1, 1); issue(2, 2);

  // Epilogue mapping: jq = quad within 8-row group (0/1), t = tid>>1.
  const int jq = tid & 1;
  const int t  = tid >> 1;  // 0..127
  const int tt = (t < NT - 1) ? tgt_s[t] : 0;
  const bool act = (t < NT - 1);

  int st = 0;  // stage of group g
  for (int g = 0; g < NGROUP; ++g) {
    if (g >= NGROUP - NSTAGE)
      asm volatile("cp.async.wait_group 0;" ::: "memory");
    else
      asm volatile("cp.async.wait_group %0;" :: "n"(NSTAGE - 1) : "memory");
    __syncthreads();

    const int r0 = g * GROWS;
    const float s0 = rS[r0 + jq * 4 + 0];
    const float s1 = rS[r0 + jq * 4 + 1];
    const float s2 = rS[r0 + jq * 4 + 2];
    const float s3 = rS[r0 + jq * 4 + 3];
    if (act) {
      const float* col = stage + st * (GROWS * RSTRIDE) + (jq * 4) * RSTRIDE + tt;
      float4 v;
      v.x = col[0 * RSTRIDE] * s0;
      v.y = col[1 * RSTRIDE] * s1;
      v.z = col[2 * RSTRIDE] * s2;
      v.w = col[3 * RSTRIDE] * s3;
      *(float4*)&g_G[(((size_t)b * NT + t) * 2 + arr) * NY + r0 + jq * 4] = v;
    }
    __syncthreads();  // stage st free before refill

    if (g + NSTAGE < NGROUP) issue(g + NSTAGE, st);
    st = (st == NSTAGE - 1) ? 0 : st + 1;
  }
}

// ---------------------------------------------------------------------------
// Phase 2: warp per batch; lane l owns j = 4l..4l+3. Affine (A,D) warp scan
// of x[j] = a[j] + d[j]*x[j-1]. The decay side (D) is data-independent per
// step (all-1 on EOS, else fixed R2 vector), so all per-level scanned D
// multipliers are PRECOMPUTED once; the per-step inner scan only carries As.
// Coefficient rows stream through a per-warp cp.async SMEM ring, PF=14.
// ---------------------------------------------------------------------------
#define PF 14

__global__ __launch_bounds__(128) void scan_kernel(
    const float* __restrict__ R, const int* __restrict__ target,
    float* __restrict__ out) {
  extern __shared__ float ring[];  // [4 warps][16 slots][256 floats] = 64 KB
  const int l = threadIdx.x & 31;
  const int w = threadIdx.x >> 5;
  const int b = blockIdx.x * 4 + w;
  const unsigned FULL = 0xffffffffu;

  float* wring = ring + w * (16 * 256);
  const float* __restrict__ gG = (const float*)g_G4;
  const size_t gbase = (size_t)b * NT * 256;

  auto issue_row = [&](int r) {
    const float* s1 = gG + gbase + (size_t)r * 256 + l * 4;
    float* d1 = wring + (r & 15) * 256 + l * 4;
    unsigned da = (unsigned)__cvta_generic_to_shared(d1);
    asm volatile(
        "cp.async.cg.shared.global [%0], [%1], 16;\n"
        "cp.async.cg.shared.global [%2], [%3], 16;\n"
        :: "r"(da), "l"(s1), "r"(da + 512), "l"(s1 + 128) : "memory");
    asm volatile("cp.async.commit_group;" ::: "memory");
  };

#pragma unroll
  for (int k = 0; k < PF; ++k) issue_row(k);

  unsigned em[4];
#pragma unroll
  for (int m = 0; m < 4; ++m) {
    const int tg = target[b * NT + l + 32 * m];
    em[m] = __ballot_sync(FULL, tg == EOS_);
  }

  float r2[4];
#pragma unroll
  for (int k = 0; k < 4; ++k)
    r2[k] = R[((size_t)b * NY + 4 * l + k) * 3 + 2];
  const float r2p = __shfl_up_sync(FULL, r2[3], 1);
  const float dsh0 = (l == 0) ? 1.0f : r2p;

  // ---- precomputed non-EOS decay constants ----
  // Local cumulative products D0..D3 (d0=dsh0, d1..d3 = r2[0..2]).
  const float Dn0 = dsh0;
  const float Dn1 = Dn0 * r2[0];
  const float Dn2 = Dn1 * r2[1];
  const float Dn3 = Dn2 * r2[2];
  // Per-level scanned multipliers: Dsc[k] = prod of Dn3 over lanes
  // (l-2^k+1 .. l), i.e. the Ds value consumed at scan level k.
  float Dsc[5];
  {
    float Dl = Dn3;
#pragma unroll
    for (int k = 0; k < 5; ++k) {
      const int off = 1 << k;
      Dsc[k] = Dl;
      const float Do = __shfl_up_sync(FULL, Dl, off);
      if (l >= off) Dl *= Do;
    }
  }

  // row0[j] = prod_{k=1..j} (eos0 ? 1 : R2[k])
  const bool eos0 = em[0] & 1u;
  const float m0v = (l == 0) ? 1.0f : (eos0 ? 1.0f : r2[0]);
  const float m1v = eos0 ? 1.0f : r2[1];
  const float m2v = eos0 ? 1.0f : r2[2];
  const float m3v = eos0 ? 1.0f : r2[3];
  const float P0 = m0v, P1 = P0 * m1v, P2 = P1 * m2v, P3 = P2 * m3v;
  float Pw = P3;
#pragma unroll
  for (int off = 1; off < 32; off <<= 1) {
    const float Po = __shfl_up_sync(FULL, Pw, off);
    if (l >= off) Pw *= Po;
  }
  float pin = __shfl_up_sync(FULL, Pw, 1);
  if (l == 0) pin = 1.0f;
  float row0 = P0 * pin, row1 = P1 * pin, row2 = P2 * pin, row3 = P3 * pin;

  asm volatile("cp.async.wait_group 13;" ::: "memory");  // row 0 ready
  float4 cpc = *(const float4*)(wring + 0 * 256 + l * 4);
  float4 cpi = *(const float4*)(wring + 0 * 256 + 128 + l * 4);

  for (int i = 0; i < NT - 1; ++i) {
    const int rf = i + PF;
    if (rf <= 127) issue_row(rf);
    else asm volatile("cp.async.commit_group;" ::: "memory");

    asm volatile("cp.async.wait_group 13;" ::: "memory");
    const int slot = (i + 1) & 15;
    const float4 npc = *(const float4*)(wring + slot * 256 + l * 4);
    const float4 npi = *(const float4*)(wring + slot * 256 + 128 + l * 4);

    const int ts = i + 1;
    const unsigned ew = (ts & 64) ? ((ts & 32) ? em[3] : em[2])
                                  : ((ts & 32) ? em[1] : em[0]);
    const bool eos = (ew >> (ts & 31)) & 1u;
    const float d1 = eos ? 1.0f : r2[0];
    const float d2 = eos ? 1.0f : r2[1];
    const float d3 = eos ? 1.0f : r2[2];

    // a_full[j] = row[j-1]*pC[j-1] + row[j]*pI[j]   (j=0: row[0]*pI[0])
    const float q3 = row3 * cpc.w;
    float qp = __shfl_up_sync(FULL, q3, 1);
    if (l == 0) qp = 0.0f;
    const float a0 = fmaf(row0, cpi.x, qp);
    const float a1 = fmaf(row1, cpi.y, row0 * cpc.x);
    const float a2 = fmaf(row2, cpi.z, row1 * cpc.y);
    const float a3 = fmaf(row3, cpi.w, row2 * cpc.z);

    // local affine prefixes (A side only; D side precomputed)
    const float A0 = a0;
    const float A1 = fmaf(d1, A0, a1);
    const float A2 = fmaf(d2, A1, a2);
    const float A3 = fmaf(d3, A2, a3);

    // inclusive warp scan of As with precomputed D multipliers
    float As = A3;
#pragma unroll
    for (int k = 0; k < 5; ++k) {
      const int off = 1 << k;
      const float Dk = eos ? 1.0f : Dsc[k];
      const float Ao = __shfl_up_sync(FULL, As, off);
      if (l >= off) As = fmaf(Dk, Ao, As);
    }
    float xin = __shfl_up_sync(FULL, As, 1);
    if (l == 0) xin = 0.0f;

    row0 = fmaf(eos ? 1.0f : Dn0, xin, A0);
    row1 = fmaf(eos ? 1.0f : Dn1, xin, A1);
    row2 = fmaf(eos ? 1.0f : Dn2, xin, A2);
    row3 = As;  // = A3 + D3*xin

    cpc = npc; cpi = npi;
  }

  if (l == 31) out[b] = row3;
}

// ---------------------------------------------------------------------------
extern "C" void kernel_launch(void* const* d_in, const int* in_sizes, int n_in,
                              void* d_out, int out_size) {
  const float* pred   = (const float*)d_in[0];
  const float* R      = (const float*)d_in[1];
  const float* I      = (const float*)d_in[2];
  const int*   target = (const int*)d_in[3];

  cudaFuncSetAttribute(gather_kernel,
                       cudaFuncAttributeMaxDynamicSharedMemorySize, SMEM_G);
  const int smem_s = 4 * 16 * 256 * (int)sizeof(float);  // 65536 B
  cudaFuncSetAttribute(scan_kernel,
                       cudaFuncAttributeMaxDynamicSharedMemorySize, smem_s);

  gather_kernel<<<B_ * 2, 256, SMEM_G>>>(pred, R, I, target);
  scan_kernel<<<B_ / 4, 128, smem_s>>>(R, target, (float*)d_out);
}